// round 17
// baseline (speedup 1.0000x reference)
#include <cuda_runtime.h>
#include <cuda_fp16.h>
#include <cstdint>

#define BATCH 16
#define CDIM 256
#define HWDIM 2304
#define PB (CDIM * HWDIM)

#define STG2 30720u                 // Ahi+Alo+Bhi, 128 rows x 80B each
#define STG1 20480u                 // Ahi+Bhi
#define SMEM_G2 (3 * STG2)          // 92160 (3-stage)
#define SMEM_G1 (4 * STG1)          // 81920 (4-stage)

#define NPART_PER_B 576             // prep CTAs per batch (8 x 72)
#define NPART (BATCH * NPART_PER_B) // 9216

// ---------------------------------------------------------------------------
// Device scratch (allocation-free)
// ---------------------------------------------------------------------------
__device__ float g_inv[BATCH];
__device__ float g_part[NPART];
__device__ __align__(1024) __half g_Xhi[(size_t)BATCH * PB];
__device__ __align__(1024) __half g_XThi[(size_t)BATCH * PB];
__device__ __align__(1024) __half g_Whi[CDIM * CDIM];
__device__ __align__(1024) __half g_Wlo[CDIM * CDIM];
__device__ __align__(1024) __half g_Shat[(size_t)BATCH * HWDIM * HWDIM];  // 170MB, scaled S
__device__ __align__(1024) __half g_Tf16[(size_t)BATCH * PB];             // fp16 T (flat [256,2304])
__device__ __align__(1024) __half g_TThi[(size_t)BATCH * PB];

// ---------------------------------------------------------------------------
// fp16 helpers
// ---------------------------------------------------------------------------
__device__ __forceinline__ uint32_t packhf(float a, float b) {
    __half ha = __float2half_rn(a), hb = __float2half_rn(b);
    return (uint32_t)__half_as_ushort(ha) | ((uint32_t)__half_as_ushort(hb) << 16);
}

// ---------------------------------------------------------------------------
// Fused x preprocessing: ONE read of x produces
//   - flat fp16 Xhi            (packed uint32 stores)
//   - transposed fp16 XThi     ([2304,256], packed uint32 stores)
//   - per-CTA sumsq partial    (fixed 32x32-tile partition -> deterministic)
// grid (72, 8, 16), 256 threads; x viewed [256(c), 2304(p)] per batch
// ---------------------------------------------------------------------------
__global__ void prep_x(const float* __restrict__ x,
                       __half* __restrict__ flat, __half* __restrict__ tr) {
    __shared__ float t[32][33];
    __shared__ float red[256];
    const int bz = blockIdx.z;
    const size_t off = (size_t)bz * PB;
    const int c0 = blockIdx.x * 32, r0 = blockIdx.y * 32;
    const int xi = threadIdx.x & 31, y0 = threadIdx.x >> 5;
    float s = 0.f;
#pragma unroll
    for (int yy = y0; yy < 32; yy += 8) {
        float v = x[off + (size_t)(r0 + yy) * HWDIM + c0 + xi];
        t[yy][xi] = v;
        s += v * v;
    }
    __syncthreads();
    const int sx = threadIdx.x & 15, sy = threadIdx.x >> 4;
    // flat cast write: pairs along columns
#pragma unroll
    for (int rr = sy; rr < 32; rr += 16) {
        uint32_t pk = packhf(t[rr][2 * sx], t[rr][2 * sx + 1]);
        *(uint32_t*)(flat + off + (size_t)(r0 + rr) * HWDIM + c0 + 2 * sx) = pk;
    }
    // transposed write: XThi[(c0+cc)*256 + r0+2sx], pairs along rows
#pragma unroll
    for (int cc = sy; cc < 32; cc += 16) {
        uint32_t pk = packhf(t[2 * sx][cc], t[2 * sx + 1][cc]);
        *(uint32_t*)(tr + off + (size_t)(c0 + cc) * CDIM + r0 + 2 * sx) = pk;
    }
    // sumsq partial
    red[threadIdx.x] = s;
    __syncthreads();
    for (int o = 128; o > 0; o >>= 1) {
        if (threadIdx.x < (unsigned)o) red[threadIdx.x] += red[threadIdx.x + o];
        __syncthreads();
    }
    if (threadIdx.x == 0)
        g_part[bz * NPART_PER_B + blockIdx.y * 72 + blockIdx.x] = red[0];
}

// grid: BATCH x 256 threads; reduce 576 partials per batch -> 1/sum
__global__ void finalize_inv() {
    const int b = blockIdx.x;
    float s = 0.f;
    for (int i = threadIdx.x; i < NPART_PER_B; i += 256)
        s += g_part[b * NPART_PER_B + i];
    __shared__ float red[256];
    red[threadIdx.x] = s;
    __syncthreads();
    for (int off = 128; off > 0; off >>= 1) {
        if (threadIdx.x < (unsigned)off) red[threadIdx.x] += red[threadIdx.x + off];
        __syncthreads();
    }
    if (threadIdx.x == 0) g_inv[b] = 1.0f / red[0];
}

// f32 -> fp16 hi/lo split (flat) — W only
__global__ void split_flat(const float4* __restrict__ in,
                           uint2* __restrict__ hi, uint2* __restrict__ lo, int n4) {
    int i = blockIdx.x * blockDim.x + threadIdx.x;
    if (i >= n4) return;
    float4 v = in[i];
    __half h0 = __float2half_rn(v.x), h1 = __float2half_rn(v.y);
    __half h2 = __float2half_rn(v.z), h3 = __float2half_rn(v.w);
    uint2 hp, lp;
    hp.x = (uint32_t)__half_as_ushort(h0) | ((uint32_t)__half_as_ushort(h1) << 16);
    hp.y = (uint32_t)__half_as_ushort(h2) | ((uint32_t)__half_as_ushort(h3) << 16);
    lp.x = packhf(v.x - __half2float(h0), v.y - __half2float(h1));
    lp.y = packhf(v.z - __half2float(h2), v.w - __half2float(h3));
    hi[i] = hp;
    lo[i] = lp;
}

// fp16 transpose (for TT = transpose of fp16 T view), packed stores
__global__ void transpose_h(const __half* __restrict__ in,
                            __half* __restrict__ hi, int rows, int cols) {
    __shared__ float t[32][33];
    const size_t off = (size_t)blockIdx.z * rows * cols;
    const int c0 = blockIdx.x * 32, r0 = blockIdx.y * 32;
    const int x = threadIdx.x & 31, y0 = threadIdx.x >> 5;
#pragma unroll
    for (int yy = y0; yy < 32; yy += 8)
        t[yy][x] = __half2float(in[off + (size_t)(r0 + yy) * cols + c0 + x]);
    __syncthreads();
    const int sx = threadIdx.x & 15, sy = threadIdx.x >> 4;
#pragma unroll
    for (int cc = sy; cc < 32; cc += 16) {
        uint32_t pk = packhf(t[2 * sx][cc], t[2 * sx + 1][cc]);
        *(uint32_t*)(hi + off + (size_t)(c0 + cc) * rows + r0 + 2 * sx) = pk;
    }
}

// ---------------------------------------------------------------------------
// PTX helpers (sm_80 baseline — compiles on plain compute_103)
// ---------------------------------------------------------------------------
__device__ __forceinline__ uint32_t s2u(const void* p) {
    uint32_t a;
    asm("{ .reg .u64 t; cvta.to.shared.u64 t, %1; cvt.u32.u64 %0, t; }" : "=r"(a) : "l"(p));
    return a;
}
__device__ __forceinline__ void cp16(uint32_t d, const void* g) {
    asm volatile("cp.async.cg.shared.global [%0], [%1], 16;" :: "r"(d), "l"(g));
}
#define LDM4(r, addr) \
    asm volatile("ldmatrix.sync.aligned.m8n8.x4.shared.b16 {%0,%1,%2,%3}, [%4];" \
        : "=r"((r)[0]), "=r"((r)[1]), "=r"((r)[2]), "=r"((r)[3]) : "r"(addr))
#define MMAH(c, a0, a1, a2, a3, b0, b1) \
    asm volatile("mma.sync.aligned.m16n8k16.row.col.f32.f16.f16.f32 " \
        "{%0,%1,%2,%3}, {%4,%5,%6,%7}, {%8,%9}, {%0,%1,%2,%3};" \
        : "+f"((c)[0]), "+f"((c)[1]), "+f"((c)[2]), "+f"((c)[3]) \
        : "r"(a0), "r"(a1), "r"(a2), "r"(a3), "r"(b0), "r"(b1))

// ---------------------------------------------------------------------------
// fp16 mma.sync GEMM, CTA 128x128, warp tile 64x32, KC=32, NSTG-stage cp.async
//   D[m,n] = sum_k A[m,k]*B[n,k]   (K-major fp16)
// TERMS=2: ahi*bhi + alo*bhi  (= A*Bhi, A exact)       [G2: 3-stage]
// TERMS=1: ahi*bhi                                      [G1/G3: 4-stage]
// EPI 0: Shat = relu(acc/256)^2 -> g_Shat (fp16)
// EPI 1: T = acc + bias[row]     -> g_Tf16 (fp16, ld 2304)
// EPI 2: Y = acc * inv^2*65536   -> outY (f32, ld 256)
// ---------------------------------------------------------------------------
template <int EPI, int TERMS, int NSTG>
__global__ void __launch_bounds__(256, 2)
mm_fp16(const __half* __restrict__ Ah, const __half* __restrict__ Al,
        const __half* __restrict__ Bh,
        int lda, int ldb, size_t bA, size_t bB, int K,
        const float* __restrict__ bias, float* __restrict__ outY)
{
    constexpr uint32_t STG = (TERMS == 2) ? STG2 : STG1;
    constexpr uint32_t oBh = (TERMS == 2) ? 20480u : 10240u;

    extern __shared__ char smv[];
    const uint32_t sb = s2u(smv);
    const int tid = threadIdx.x;
    const int bz = blockIdx.z;
    const int m0 = blockIdx.y * 128, n0 = blockIdx.x * 128;
    const int w = tid >> 5, l = tid & 31;
    const int wm = w >> 2, wn = w & 3;       // 2 x 4 warps, warp tile 64x32

    const int r = tid >> 1, c = tid & 1;
    const __half* pAh = Ah + (size_t)bz * bA + (size_t)(m0 + r) * lda + c * 16;
    const __half* pAl = (TERMS == 2) ? (Al + (size_t)(m0 + r) * lda + c * 16) : nullptr;
    const __half* pBh = Bh + (size_t)bz * bB + (size_t)(n0 + r) * ldb + c * 16;
    const uint32_t dA = sb + r * 80 + c * 32;
    const uint32_t dB = sb + oBh + r * 80 + c * 32;

    const int sub = l >> 3;
    const uint32_t aOff = (uint32_t)((wm * 64 + (sub & 1) * 8 + (l & 7)) * 80 + (sub >> 1) * 16);
    const uint32_t bOff = (uint32_t)(oBh + (wn * 32 + (l >> 4) * 8 + (l & 7)) * 80 + ((l >> 3) & 1) * 16);

    float acc[4][4][4];
#pragma unroll
    for (int i = 0; i < 4; i++)
#pragma unroll
        for (int j = 0; j < 4; j++)
#pragma unroll
            for (int q = 0; q < 4; q++) acc[i][j][q] = 0.f;

#define LOAD_STAGE(kc, slot) do { \
        const uint32_t so = (uint32_t)(slot) * STG; \
        const int ko = (kc) * 32; \
        cp16(dA + so,      pAh + ko); \
        cp16(dA + so + 16, pAh + ko + 8); \
        cp16(dB + so,      pBh + ko); \
        cp16(dB + so + 16, pBh + ko + 8); \
        if (TERMS == 2) { \
            cp16(dA + so + 10240, pAl + ko); \
            cp16(dA + so + 10256, pAl + ko + 8); \
        } \
        asm volatile("cp.async.commit_group;"); \
    } while (0)

    const int KN = K / 32;
#pragma unroll
    for (int p = 0; p < NSTG - 1; p++) LOAD_STAGE(p, p);

    int slot = 0;
    for (int kc = 0; kc < KN; kc++) {
        if (NSTG == 4) asm volatile("cp.async.wait_group 2;");
        else           asm volatile("cp.async.wait_group 1;");
        __syncthreads();
        if (kc + NSTG - 1 < KN) LOAD_STAGE(kc + NSTG - 1, (kc + NSTG - 1) % NSTG);
        const uint32_t s0 = sb + slot * STG;
        slot++; if (slot == NSTG) slot = 0;
#pragma unroll
        for (int ks = 0; ks < 2; ks++) {
            uint32_t bfh[4][2];
            const uint32_t b0a = s0 + bOff + ks * 32;
#pragma unroll
            for (int p = 0; p < 2; p++) {
                uint32_t t4[4];
                LDM4(t4, b0a + p * (16 * 80));
                bfh[2 * p][0] = t4[0]; bfh[2 * p][1] = t4[1];
                bfh[2 * p + 1][0] = t4[2]; bfh[2 * p + 1][1] = t4[3];
            }
            const uint32_t a0a = s0 + aOff + ks * 32;
#pragma unroll
            for (int i = 0; i < 4; i++) {
                uint32_t ah[4];
                LDM4(ah, a0a + i * 1280);
#pragma unroll
                for (int j = 0; j < 4; j++)
                    MMAH(acc[i][j], ah[0], ah[1], ah[2], ah[3], bfh[j][0], bfh[j][1]);
                if (TERMS == 2) {
                    uint32_t al4[4];
                    LDM4(al4, a0a + i * 1280 + 10240);
#pragma unroll
                    for (int j = 0; j < 4; j++)
                        MMAH(acc[i][j], al4[0], al4[1], al4[2], al4[3], bfh[j][0], bfh[j][1]);
                }
            }
        }
    }

    // epilogue
    float factor = 0.f;
    if (EPI == 2) {
        float inv = g_inv[bz];
        factor = inv * inv * 65536.f;
    }
    const int quad = l >> 2, tq = l & 3;
#pragma unroll
    for (int i = 0; i < 4; i++) {
#pragma unroll
        for (int half = 0; half < 2; half++) {
            const int rr = m0 + wm * 64 + i * 16 + quad + half * 8;
            float bvv = 0.f;
            if (EPI == 1) bvv = bias[rr];
#pragma unroll
            for (int j = 0; j < 4; j++) {
                const int col = n0 + wn * 32 + j * 8 + tq * 2;
                float v0 = acc[i][j][half * 2 + 0];
                float v1 = acc[i][j][half * 2 + 1];
                if (EPI == 0) {
                    v0 = fmaxf(v0 * 0.00390625f, 0.f); v0 *= v0;
                    v1 = fmaxf(v1 * 0.00390625f, 0.f); v1 *= v1;
                    size_t base = (size_t)bz * HWDIM * HWDIM + (size_t)rr * HWDIM + col;
                    *(uint32_t*)(g_Shat + base) = packhf(v0, v1);
                } else if (EPI == 1) {
                    size_t base = (size_t)bz * PB + (size_t)rr * HWDIM + col;
                    *(uint32_t*)(g_Tf16 + base) = packhf(v0 + bvv, v1 + bvv);
                } else {
                    float2 vv; vv.x = v0 * factor; vv.y = v1 * factor;
                    *(float2*)(outY + (size_t)bz * PB + (size_t)rr * CDIM + col) = vv;
                }
            }
        }
    }
#undef LOAD_STAGE
}

// ---------------------------------------------------------------------------
// Host launch — two-stream fork/join:
//   s0: prep_x ───────────────► G1 ─────────► G3
//         │(evPrep)                   (evAux)▲
//   s1: ──┴─ split ─ finalize, G2, TT ───────┘
// ---------------------------------------------------------------------------
extern "C" void kernel_launch(void* const* d_in, const int* in_sizes, int n_in,
                              void* d_out, int out_size)
{
    const float* x    = (const float*)d_in[0];
    const float* W    = (const float*)d_in[1];
    const float* bias = (const float*)d_in[2];
    float* out        = (float*)d_out;

    void *pXhi, *pXThi, *pWhi, *pWlo, *pShat, *pTThi, *pTf;
    cudaGetSymbolAddress(&pXhi,  g_Xhi);
    cudaGetSymbolAddress(&pXThi, g_XThi);
    cudaGetSymbolAddress(&pWhi,  g_Whi);
    cudaGetSymbolAddress(&pWlo,  g_Wlo);
    cudaGetSymbolAddress(&pShat, g_Shat);
    cudaGetSymbolAddress(&pTThi, g_TThi);
    cudaGetSymbolAddress(&pTf,   g_Tf16);

    static bool init_done = false;
    static cudaStream_t s1;
    static cudaEvent_t evRoot, evPrep, evAux;
    if (!init_done) {
        cudaFuncSetAttribute(mm_fp16<0, 1, 4>, cudaFuncAttributeMaxDynamicSharedMemorySize, SMEM_G1);
        cudaFuncSetAttribute(mm_fp16<1, 2, 3>, cudaFuncAttributeMaxDynamicSharedMemorySize, SMEM_G2);
        cudaFuncSetAttribute(mm_fp16<2, 1, 4>, cudaFuncAttributeMaxDynamicSharedMemorySize, SMEM_G1);
        cudaStreamCreateWithFlags(&s1, cudaStreamNonBlocking);
        cudaEventCreateWithFlags(&evRoot, cudaEventDisableTiming);
        cudaEventCreateWithFlags(&evPrep, cudaEventDisableTiming);
        cudaEventCreateWithFlags(&evAux,  cudaEventDisableTiming);
        init_done = true;
    }

    cudaStream_t s0 = 0;   // default (capture) stream

    // fork s1 from s0
    cudaEventRecord(evRoot, s0);
    cudaStreamWaitEvent(s1, evRoot, 0);

    // s0: fused x prep (cast + transpose + sumsq partials in one read)
    prep_x<<<dim3(HWDIM / 32, CDIM / 32, BATCH), 256, 0, s0>>>(
        x, (__half*)pXhi, (__half*)pXThi);
    cudaEventRecord(evPrep, s0);

    // s1: W split (independent), then prep-dependent aux chain
    split_flat<<<(CDIM * CDIM / 4 + 255) / 256, 256, 0, s1>>>(
        (const float4*)W, (uint2*)pWhi, (uint2*)pWlo, CDIM * CDIM / 4);
    cudaStreamWaitEvent(s1, evPrep, 0);
    finalize_inv<<<BATCH, 256, 0, s1>>>();
    mm_fp16<1, 2, 3><<<dim3(HWDIM / 128, CDIM / 128, BATCH), 256, SMEM_G2, s1>>>(
        (const __half*)pWhi, (const __half*)pWlo, (const __half*)pXThi,
        CDIM, CDIM, 0, (size_t)PB, CDIM, bias, nullptr);
    {
        dim3 g(CDIM / 32, HWDIM / 32, BATCH);
        transpose_h<<<g, 256, 0, s1>>>((const __half*)pTf, (__half*)pTThi, HWDIM, CDIM);
    }
    cudaEventRecord(evAux, s1);

    // s0: G1 (Xhi + XThi both produced in-stream by prep)
    mm_fp16<0, 1, 4><<<dim3(HWDIM / 128, HWDIM / 128, BATCH), 256, SMEM_G1, s0>>>(
        (const __half*)pXhi, nullptr, (const __half*)pXThi,
        CDIM, CDIM, (size_t)PB, (size_t)PB, CDIM, nullptr, nullptr);

    // join: G3 needs Shat (s0), TThi + inv (s1 via evAux)
    cudaStreamWaitEvent(s0, evAux, 0);
    mm_fp16<2, 1, 4><<<dim3(CDIM / 128, HWDIM / 128, BATCH), 256, SMEM_G1, s0>>>(
        (const __half*)pShat, nullptr, (const __half*)pTThi,
        HWDIM, HWDIM, (size_t)HWDIM * HWDIM, (size_t)PB, HWDIM, nullptr, out);
}